// round 14
// baseline (speedup 1.0000x reference)
#include <cuda_runtime.h>
#include <cuda_fp16.h>

#define DIM_H 512
#define NIMG  128
#define NROWS (NIMG * DIM_H)           // 65536 row-lines
#define INV_SCALE (1.0f / (512.0f * 512.0f))
#define HPL 584                         // half2 plane pitch (all kernels)
#define NGRP 33                         // column groups of 8 (257 cols padded to 264)
#define GRP  4096                       // half2 per group = 512*8
#define IMGS (NGRP * GRP)               // half2 per image = 135168

// Scratch: [img][group][h][wi] in fp16 complex, 69 MB. Group = 8 adjacent spectrum cols.
__device__ __half2 g_scratch[(size_t)NIMG * IMGS];
// Baked Hermitianized filter (fp32): [pw 0..256][ph 0..511], scale+untangle folded.
__device__ float2 g_filter[(size_t)257 * 512];
// Twiddle power tables (L1-resident, 4KB):
// g_twA[(r-1)*64 + t]  = exp(-2*pi*i * t*r   / 512), r=1..7, t=0..63
// g_twB[(r-1)*8  + tp] = exp(-2*pi*i * 8*tp*r/ 512), r=1..7, tp=0..7
__device__ float2 g_twA[7 * 64];
__device__ float2 g_twB[7 * 8];

// ---------------- packed f32x2 complex primitives ----------------
typedef unsigned long long u64c;   // one complex: lo = re, hi = im

__device__ __forceinline__ u64c pk2(float x, float y){
    u64c r; asm("mov.b64 %0, {%1, %2};" : "=l"(r) : "f"(x), "f"(y)); return r;
}
__device__ __forceinline__ float2 up2(u64c v){
    float2 r; asm("mov.b64 {%0, %1}, %2;" : "=f"(r.x), "=f"(r.y) : "l"(v)); return r;
}
__device__ __forceinline__ u64c addp(u64c a, u64c b){
    u64c r; asm("add.rn.f32x2 %0, %1, %2;" : "=l"(r) : "l"(a), "l"(b)); return r;
}
__device__ __forceinline__ u64c mulp(u64c a, u64c b){
    u64c r; asm("mul.rn.f32x2 %0, %1, %2;" : "=l"(r) : "l"(a), "l"(b)); return r;
}
__device__ __forceinline__ u64c fmap(u64c a, u64c b, u64c c){
    u64c r; asm("fma.rn.f32x2 %0, %1, %2, %3;" : "=l"(r) : "l"(a), "l"(b), "l"(c)); return r;
}
// a - b, exact
__device__ __forceinline__ u64c subp(u64c a, u64c b){
    return fmap(b, pk2(-1.0f, -1.0f), a);
}
// rot<S>(v) = i*S*v
template<int S>
__device__ __forceinline__ u64c rotp(u64c v){
    float2 f = up2(v);
    return (S > 0) ? pk2(-f.y, f.x) : pk2(f.y, -f.x);
}

// packed * scalar-complex twiddle; S=+1 conjugates the twiddle (inverse FFT).
template<int S>
__device__ __forceinline__ u64c cmul_t(u64c a, float2 b){
    float by = (S > 0) ? -b.y : b.y;
    float2 f = up2(a);
    return pk2(f.x*b.x - f.y*by, f.x*by + f.y*b.x);
}

__device__ __forceinline__ __half2 pack_h2(float re, float im){ return __floats2half2_rn(re, im); }
__device__ __forceinline__ float2 unpack_h2(__half2 v){ return __half22float2(v); }
__device__ __forceinline__ float2 unpack_u(unsigned u){
    __half2 h = *reinterpret_cast<__half2*>(&u);
    return __half22float2(h);
}
__device__ __forceinline__ unsigned pack_u(float x, float y){
    __half2 h = __floats2half2_rn(x, y);
    return *reinterpret_cast<unsigned*>(&h);
}

// storage-position <-> frequency permutation: swap low two octal digits (involution, keeps bit 8)
__device__ __forceinline__ int kmap9(int p){
    return (p & 448) | ((p & 7) << 3) | ((p >> 3) & 7);
}

// 8-point DFT, packed, natural in/out: out[r] = sum_j in[j] * exp(S*2*pi*i*j*r/8)
template<int S>
__device__ __forceinline__ void dft8p(u64c* a){
    u64c t0=addp(a[0],a[4]), t1=subp(a[0],a[4]);
    u64c t2=addp(a[2],a[6]), t3=subp(a[2],a[6]);
    u64c t3r=rotp<S>(t3);
    u64c E0=addp(t0,t2), E2=subp(t0,t2), E1=addp(t1,t3r), E3=subp(t1,t3r);
    u64c u0=addp(a[1],a[5]), u1=subp(a[1],a[5]);
    u64c u2=addp(a[3],a[7]), u3=subp(a[3],a[7]);
    u64c u3r=rotp<S>(u3);
    u64c O0=addp(u0,u2), O2=subp(u0,u2), O1=addp(u1,u3r), O3=subp(u1,u3r);
    const float c = 0.70710678118654752f;
    u64c cc = pk2(c, c);
    O1 = mulp(cc, addp(O1, rotp<S>(O1)));          // *(c + i*S*c)
    u64c O2r = rotp<S>(O2);                         // *(i*S)
    O3 = mulp(cc, subp(rotp<S>(O3), O3));           // *(-c + i*S*c)
    a[0]=addp(E0,O0); a[4]=subp(E0,O0);
    a[1]=addp(E1,O1); a[5]=subp(E1,O1);
    a[2]=addp(E2,O2r); a[6]=subp(E2,O2r);
    a[3]=addp(E3,O3); a[7]=subp(E3,O3);
}

// Table-driven twiddle applies (replaces chain powering): 7 LDG.64 + 7 cmuls.
template<int S>
__device__ __forceinline__ void applyA(u64c* a, int t){
    #pragma unroll
    for (int r = 1; r < 8; ++r)
        a[r] = cmul_t<S>(a[r], g_twA[(r-1)*64 + t]);
}
template<int S>
__device__ __forceinline__ void applyB(u64c* a, int tp){
    #pragma unroll
    for (int r = 1; r < 8; ++r)
        a[r] = cmul_t<S>(a[r], g_twB[(r-1)*8 + tp]);
}

// ---------- fp16-plane FFTs, packed state, table twiddles ----------
// Forward 512-pt FFT. In: a[j] = x[t + 64*j]. Out: a[q] = X[kmap9(t + 64*q)].
__device__ __forceinline__ void fft512_fwd_h(u64c* a, __half2* pl, int t){
    dft8p<-1>(a);
    applyA<-1>(a, t);
    #pragma unroll
    for (int r = 0; r < 8; ++r){ float2 f = up2(a[r]); pl[r*72 + t] = pack_h2(f.x, f.y); }
    __syncthreads();
    int tp = t & 7, rr = t >> 3;
    #pragma unroll
    for (int j = 0; j < 8; ++j){ float2 f = unpack_h2(pl[rr*72 + tp + 8*j]); a[j] = pk2(f.x, f.y); }
    dft8p<-1>(a);
    applyB<-1>(a, tp);
    __syncthreads();
    #pragma unroll
    for (int r1 = 0; r1 < 8; ++r1){ float2 f = up2(a[r1]); pl[rr*72 + r1*9 + tp] = pack_h2(f.x, f.y); }
    __syncthreads();
    #pragma unroll
    for (int k = 0; k < 8; ++k){ float2 f = unpack_h2(pl[t*9 + k]); a[k] = pk2(f.x, f.y); }
    dft8p<-1>(a);
}

// Inverse (unscaled) 512-pt FFT. In: a[q] = S[kmap9(t + 64*q)]. Out: a[j] = y[t + 64*j].
__device__ __forceinline__ void fft512_inv_h(u64c* a, __half2* pl, int t){
    dft8p<1>(a);
    int tp = t & 7, rr = t >> 3;
    #pragma unroll
    for (int k = 0; k < 8; ++k){ float2 f = up2(a[k]); pl[t*9 + k] = pack_h2(f.x, f.y); }
    __syncthreads();
    #pragma unroll
    for (int r1 = 0; r1 < 8; ++r1){ float2 f = unpack_h2(pl[rr*72 + r1*9 + tp]); a[r1] = pk2(f.x, f.y); }
    applyB<1>(a, tp);
    dft8p<1>(a);
    __syncthreads();
    #pragma unroll
    for (int j = 0; j < 8; ++j){ float2 f = up2(a[j]); pl[rr*72 + tp + 8*j] = pack_h2(f.x, f.y); }
    __syncthreads();
    #pragma unroll
    for (int r = 0; r < 8; ++r){ float2 f = unpack_h2(pl[r*72 + t]); a[r] = pk2(f.x, f.y); }
    applyA<1>(a, t);
    dft8p<1>(a);
}

// ---------------------------------------------------------------------------
// Kernel 0: bake Hermitianized filter + twiddle power tables.
// ---------------------------------------------------------------------------
__global__ void k_bake_filter(const float* __restrict__ Hr, const float* __restrict__ Hi){
    int pw = blockIdx.x;          // 0..256
    int ph = threadIdx.x;         // 0..511
    if (pw == 0){
        if (ph < 448){
            int r = (ph >> 6) + 1, t = ph & 63;
            float s, c;
            sincosf(-6.283185307179586f * (float)((t * r) & 511) / 512.0f, &s, &c);
            g_twA[ph] = make_float2(c, s);
        } else if (ph < 504){
            int idx = ph - 448;
            int r = (idx >> 3) + 1, tp = idx & 7;
            float s, c;
            sincosf(-6.283185307179586f * (float)((8 * tp * r) & 511) / 512.0f, &s, &c);
            g_twB[idx] = make_float2(c, s);
        }
    }
    int kh = kmap9(ph), kw = kmap9(pw);
    int nh = (512 - kh) & 511, nw = (512 - kw) & 511;
    int s0 = kh * 512 + kw;
    int s1 = nh * 512 + nw;
    float re = 0.25f * (Hr[s0] + Hr[s1]);
    float im = 0.25f * (Hi[s0] - Hi[s1]);
    g_filter[pw * 512 + ph] = make_float2(re * INV_SCALE, im * INV_SCALE);
}

// ---------------------------------------------------------------------------
// Kernel 1: paired forward FFT along W. 64 threads = one FFT pair per block.
// ---------------------------------------------------------------------------
__global__ void __launch_bounds__(64) k_fft_rows(const float* __restrict__ x){
    __shared__ __half2 sP[HPL];
    int t = threadIdx.x;
    int pair = blockIdx.x;               // 0..32767
    int img  = pair >> 8;
    int h0   = (pair & 255) * 2;
    const float* x0 = x + (size_t)pair * 1024;
    const float* x1 = x0 + 512;

    u64c a[8];
    #pragma unroll
    for (int j = 0; j < 8; ++j) a[j] = pk2(x0[t + 64*j], x1[t + 64*j]);

    fft512_fwd_h(a, sP, t);

    __syncthreads();   // FFT's last plane reads done; plane reusable as staging
    #pragma unroll
    for (int q = 0; q < 8; ++q){ float2 f = up2(a[q]); sP[t + 64*q] = pack_h2(f.x, f.y); }
    __syncthreads();

    __half2* ib = g_scratch + (size_t)img * IMGS;
    int rr = t >> 3, tp = t & 7;
    #pragma unroll
    for (int q = 0; q < 4; ++q){
        int p = t + 64*q;
        int pm = p ? kmap9(512 - kmap9(p)) : 0;
        float2 A = unpack_h2(sP[p]);
        float2 B = unpack_h2(sP[pm]);
        unsigned off = (unsigned)(8*q + rr) * GRP + tp;
        ib[off + h0*8]       = pack_h2(A.x + B.x, A.y - B.y);
        ib[off + (h0+1)*8]   = pack_h2(A.y + B.y, B.x - A.x);
    }
    if (t == 0){   // p = 256, self-mirror: group 32, wi 0
        float2 A = unpack_h2(sP[256]);
        unsigned off = 32u * GRP;
        ib[off + h0*8]     = pack_h2(2.0f * A.x, 0.0f);
        ib[off + (h0+1)*8] = pack_h2(2.0f * A.y, 0.0f);
    }
}

// ---------------------------------------------------------------------------
// Kernel 2: per image, one group of 8 spectrum columns per block (256 thr).
// ---------------------------------------------------------------------------
#define SHP 513   // uint pitch per column in staging buffer (conflict-free)
__global__ void __launch_bounds__(256) k_cols(void){
    __shared__ __half2 sP[4][HPL];
    __shared__ unsigned sH[8 * SHP];
    int tid = threadIdx.x;

    int img = blockIdx.x / NGRP;
    int g   = blockIdx.x % NGRP;
    uint4* gbase = (uint4*)(g_scratch + (size_t)img * IMGS + (size_t)g * GRP);

    // stage-in: 1024 uint4 = 4096 half2 (full group), perfectly coalesced
    #pragma unroll
    for (int it = 0; it < 4; ++it){
        int idx = it * 256 + tid;        // 0..1023
        uint4 v = gbase[idx];
        int h  = idx >> 1;
        int wb = (idx & 1) * 4;
        sH[(wb+0)*SHP + h] = v.x;
        sH[(wb+1)*SHP + h] = v.y;
        sH[(wb+2)*SHP + h] = v.z;
        sH[(wb+3)*SHP + h] = v.w;
    }
    __syncthreads();

    int line = tid >> 6, t = tid & 63;
    #pragma unroll
    for (int half = 0; half < 2; ++half){
        int wi = line + half * 4;
        u64c a[8];
        #pragma unroll
        for (int j = 0; j < 8; ++j){
            float2 f = unpack_u(sH[wi*SHP + t + 64*j]);
            a[j] = pk2(f.x, f.y);
        }

        fft512_fwd_h(a, sP[line], t);    // first plane write safe: prior
                                         // sync (stage-in / end of half 0)

        int pw = g * 8 + wi; if (pw > 256) pw = 256;
        const float2* frow = g_filter + (size_t)pw * 512 + t;
        #pragma unroll
        for (int q = 0; q < 8; ++q) a[q] = cmul_t<-1>(a[q], frow[64*q]);

        __syncthreads();   // fwd's last plane reads done before inv writes

        fft512_inv_h(a, sP[line], t);

        __syncthreads();   // inv's last plane reads done before next fwd / exit
        #pragma unroll
        for (int j = 0; j < 8; ++j){
            float2 f = up2(a[j]);
            sH[wi*SHP + t + 64*j] = pack_u(f.x, f.y);
        }
    }
    __syncthreads();

    // stage-out
    #pragma unroll
    for (int it = 0; it < 4; ++it){
        int idx = it * 256 + tid;
        int h  = idx >> 1;
        int wb = (idx & 1) * 4;
        uint4 v;
        v.x = sH[(wb+0)*SHP + h];
        v.y = sH[(wb+1)*SHP + h];
        v.z = sH[(wb+2)*SHP + h];
        v.w = sH[(wb+3)*SHP + h];
        gbase[idx] = v;
    }
}

// ---------------------------------------------------------------------------
// Kernel 3: paired inverse FFT along W (C2R x2). 64 threads = one pair per block.
// ---------------------------------------------------------------------------
__global__ void __launch_bounds__(64) k_ifft_rows(float* __restrict__ out){
    __shared__ __half2 sP[HPL];
    int t = threadIdx.x;
    int pair = blockIdx.x;
    int img  = pair >> 8;
    int h0   = (pair & 255) * 2;
    const __half2* ib = g_scratch + (size_t)img * IMGS;
    int rr = t >> 3, tp = t & 7;

    // load own 4 positions of each half-spectrum; also stage for mirror gathers
    __half2 v0[4], v1[4];
    #pragma unroll
    for (int j = 0; j < 4; ++j){
        int p = t + 64*j;
        unsigned off = (unsigned)(8*j + rr) * GRP + tp;
        v0[j] = ib[off + h0*8];
        v1[j] = ib[off + (h0+1)*8];
        sP[p]       = v0[j];
        sP[288 + p] = v1[j];
    }
    if (t == 0){
        unsigned off = 32u * GRP;
        sP[256]       = ib[off + h0*8];
        sP[288 + 256] = ib[off + (h0+1)*8];
    }
    __syncthreads();

    // build permuted Z:
    // p<=256: Z = S0[p] + i*S1[p];  p>256: Z = conj(S0[ps]) + i*conj(S1[ps])
    u64c a[8];
    #pragma unroll
    for (int q = 0; q < 4; ++q){           // own values, straight from registers
        float2 A = unpack_h2(v0[q]);
        float2 B = unpack_h2(v1[q]);
        a[q] = pk2(A.x - B.y, A.y + B.x);
    }
    #pragma unroll
    for (int q = 4; q < 8; ++q){
        int p = t + 64*q;
        if (p <= 256){                     // only t==0, q==4
            float2 A = unpack_h2(sP[p]);
            float2 B = unpack_h2(sP[288 + p]);
            a[q] = pk2(A.x - B.y, A.y + B.x);
        } else {
            int ps = kmap9(512 - kmap9(p));   // in [1,255]
            float2 A = unpack_h2(sP[ps]);
            float2 B = unpack_h2(sP[288 + ps]);
            a[q] = pk2(A.x + B.y, B.x - A.y);
        }
    }
    __syncthreads();   // staging reads done before inv FFT reuses plane

    fft512_inv_h(a, sP, t);

    float* o0 = out + (size_t)pair * 1024;
    float* o1 = o0 + 512;
    #pragma unroll
    for (int j = 0; j < 8; ++j){
        float2 f = up2(a[j]);
        o0[t + 64*j] = f.x;
        o1[t + 64*j] = f.y;
    }
}

// ---------------------------------------------------------------------------
extern "C" void kernel_launch(void* const* d_in, const int* in_sizes, int n_in,
                              void* d_out, int out_size){
    const float* x  = (const float*)d_in[0];
    const float* Hr = (const float*)d_in[1];
    const float* Hi = (const float*)d_in[2];
    float* out = (float*)d_out;

    k_bake_filter<<<257, 512>>>(Hr, Hi);
    k_fft_rows<<<NROWS / 2, 64>>>(x);
    k_cols<<<NIMG * NGRP, 256>>>();
    k_ifft_rows<<<NROWS / 2, 64>>>(out);
}

// round 16
// speedup vs baseline: 1.0746x; 1.0746x over previous
#include <cuda_runtime.h>
#include <cuda_fp16.h>

#define DIM_H 512
#define NIMG  128
#define NROWS (NIMG * DIM_H)           // 65536 row-lines
#define INV_SCALE (1.0f / (512.0f * 512.0f))
#define HPL 584                         // half2 plane pitch (all kernels)
#define NGRP 33                         // column groups of 8 (257 cols padded to 264)
#define GRP  4096                       // half2 per group = 512*8
#define IMGS (NGRP * GRP)               // half2 per image = 135168

// Scratch: [img][group][h][wi] in fp16 complex, 69 MB. Group = 8 adjacent spectrum cols.
__device__ __half2 g_scratch[(size_t)NIMG * IMGS];
// Baked Hermitianized filter (fp16), UNSCALED: [pw 0..256][ph 0..511].
// Value = 0.25*(H[s0]+conj(H[s1])) — magnitude O(0.3), safely normal in fp16.
// INV_SCALE is applied separately in k_cols (packed constant multiply).
__device__ __half2 g_filter_h[(size_t)257 * 512];
// Baked twiddles: g_tws[k] = exp(-2*pi*i*k/512), k in [0,64)
__device__ float2 g_tws[64];

// ---------------- packed f32x2 complex primitives ----------------
typedef unsigned long long u64c;   // one complex: lo = re, hi = im

__device__ __forceinline__ u64c pk2(float x, float y){
    u64c r; asm("mov.b64 %0, {%1, %2};" : "=l"(r) : "f"(x), "f"(y)); return r;
}
__device__ __forceinline__ float2 up2(u64c v){
    float2 r; asm("mov.b64 {%0, %1}, %2;" : "=f"(r.x), "=f"(r.y) : "l"(v)); return r;
}
__device__ __forceinline__ u64c addp(u64c a, u64c b){
    u64c r; asm("add.rn.f32x2 %0, %1, %2;" : "=l"(r) : "l"(a), "l"(b)); return r;
}
__device__ __forceinline__ u64c mulp(u64c a, u64c b){
    u64c r; asm("mul.rn.f32x2 %0, %1, %2;" : "=l"(r) : "l"(a), "l"(b)); return r;
}
__device__ __forceinline__ u64c fmap(u64c a, u64c b, u64c c){
    u64c r; asm("fma.rn.f32x2 %0, %1, %2, %3;" : "=l"(r) : "l"(a), "l"(b), "l"(c)); return r;
}
// a - b, exact (mul by -1 is exact, then .rn add)
__device__ __forceinline__ u64c subp(u64c a, u64c b){
    return fmap(b, pk2(-1.0f, -1.0f), a);
}
// rot<S>(v) = i*S*v
template<int S>
__device__ __forceinline__ u64c rotp(u64c v){
    float2 f = up2(v);
    return (S > 0) ? pk2(-f.y, f.x) : pk2(f.y, -f.x);
}

__device__ __forceinline__ float2 cmul(float2 a, float2 b){
    return make_float2(a.x*b.x - a.y*b.y, a.x*b.y + a.y*b.x);
}
__device__ __forceinline__ float2 cconj(float2 a){ return make_float2(a.x, -a.y); }
// packed * scalar-complex (twiddle/filter application)
__device__ __forceinline__ u64c cmul_ps(u64c a, float2 b){
    float2 f = up2(a);
    return pk2(f.x*b.x - f.y*b.y, f.x*b.y + f.y*b.x);
}

__device__ __forceinline__ __half2 pack_h2(float re, float im){ return __floats2half2_rn(re, im); }
__device__ __forceinline__ float2 unpack_h2(__half2 v){ return __half22float2(v); }
__device__ __forceinline__ float2 unpack_u(unsigned u){
    __half2 h = *reinterpret_cast<__half2*>(&u);
    return __half22float2(h);
}
__device__ __forceinline__ unsigned pack_u(float x, float y){
    __half2 h = __floats2half2_rn(x, y);
    return *reinterpret_cast<unsigned*>(&h);
}

// storage-position <-> frequency permutation: swap low two octal digits (involution, keeps bit 8)
__device__ __forceinline__ int kmap9(int p){
    return (p & 448) | ((p & 7) << 3) | ((p >> 3) & 7);
}

// 8-point DFT, packed, natural in/out: out[r] = sum_j in[j] * exp(S*2*pi*i*j*r/8)
template<int S>
__device__ __forceinline__ void dft8p(u64c* a){
    u64c t0=addp(a[0],a[4]), t1=subp(a[0],a[4]);
    u64c t2=addp(a[2],a[6]), t3=subp(a[2],a[6]);
    u64c t3r=rotp<S>(t3);
    u64c E0=addp(t0,t2), E2=subp(t0,t2), E1=addp(t1,t3r), E3=subp(t1,t3r);
    u64c u0=addp(a[1],a[5]), u1=subp(a[1],a[5]);
    u64c u2=addp(a[3],a[7]), u3=subp(a[3],a[7]);
    u64c u3r=rotp<S>(u3);
    u64c O0=addp(u0,u2), O2=subp(u0,u2), O1=addp(u1,u3r), O3=subp(u1,u3r);
    const float c = 0.70710678118654752f;
    u64c cc = pk2(c, c);
    O1 = mulp(cc, addp(O1, rotp<S>(O1)));          // *(c + i*S*c)
    u64c O2r = rotp<S>(O2);                         // *(i*S)
    O3 = mulp(cc, subp(rotp<S>(O3), O3));           // *(-c + i*S*c)
    a[0]=addp(E0,O0); a[4]=subp(E0,O0);
    a[1]=addp(E1,O1); a[5]=subp(E1,O1);
    a[2]=addp(E2,O2r); a[6]=subp(E2,O2r);
    a[3]=addp(E3,O3); a[7]=subp(E3,O3);
}

// Apply w^r to a[r], r=1..7. Powers scalar (dep depth 3), application packed-scalar.
__device__ __forceinline__ void apply7p(u64c* a, float2 w1){
    float2 w2 = cmul(w1, w1);
    float2 w3 = cmul(w2, w1);
    float2 w4 = cmul(w2, w2);
    float2 w5 = cmul(w3, w2);
    float2 w6 = cmul(w3, w3);
    float2 w7 = cmul(w4, w3);
    a[1]=cmul_ps(a[1],w1); a[2]=cmul_ps(a[2],w2); a[3]=cmul_ps(a[3],w3);
    a[4]=cmul_ps(a[4],w4); a[5]=cmul_ps(a[5],w5); a[6]=cmul_ps(a[6],w6);
    a[7]=cmul_ps(a[7],w7);
}

// ---------- fp16-plane FFTs, packed state ----------
// Forward 512-pt FFT. In: a[j] = x[t + 64*j]. Out: a[q] = X[kmap9(t + 64*q)].
__device__ __forceinline__ void fft512_fwd_h(u64c* a, __half2* pl, int t,
                                             const float2* tws){
    dft8p<-1>(a);
    apply7p(a, tws[t]);
    #pragma unroll
    for (int r = 0; r < 8; ++r){ float2 f = up2(a[r]); pl[r*72 + t] = pack_h2(f.x, f.y); }
    __syncthreads();
    int tp = t & 7, rr = t >> 3;
    #pragma unroll
    for (int j = 0; j < 8; ++j){ float2 f = unpack_h2(pl[rr*72 + tp + 8*j]); a[j] = pk2(f.x, f.y); }
    dft8p<-1>(a);
    apply7p(a, tws[tp*8]);
    __syncthreads();
    #pragma unroll
    for (int r1 = 0; r1 < 8; ++r1){ float2 f = up2(a[r1]); pl[rr*72 + r1*9 + tp] = pack_h2(f.x, f.y); }
    __syncthreads();
    #pragma unroll
    for (int k = 0; k < 8; ++k){ float2 f = unpack_h2(pl[t*9 + k]); a[k] = pk2(f.x, f.y); }
    dft8p<-1>(a);
}

// Inverse (unscaled) 512-pt FFT. In: a[q] = S[kmap9(t + 64*q)]. Out: a[j] = y[t + 64*j].
__device__ __forceinline__ void fft512_inv_h(u64c* a, __half2* pl, int t,
                                             const float2* tws){
    dft8p<1>(a);
    int tp = t & 7, rr = t >> 3;
    #pragma unroll
    for (int k = 0; k < 8; ++k){ float2 f = up2(a[k]); pl[t*9 + k] = pack_h2(f.x, f.y); }
    __syncthreads();
    #pragma unroll
    for (int r1 = 0; r1 < 8; ++r1){ float2 f = unpack_h2(pl[rr*72 + r1*9 + tp]); a[r1] = pk2(f.x, f.y); }
    apply7p(a, cconj(tws[tp*8]));
    dft8p<1>(a);
    __syncthreads();
    #pragma unroll
    for (int j = 0; j < 8; ++j){ float2 f = up2(a[j]); pl[rr*72 + tp + 8*j] = pack_h2(f.x, f.y); }
    __syncthreads();
    #pragma unroll
    for (int r = 0; r < 8; ++r){ float2 f = unpack_h2(pl[r*72 + t]); a[r] = pk2(f.x, f.y); }
    apply7p(a, cconj(tws[t]));
    dft8p<1>(a);
}

// ---------------------------------------------------------------------------
// Kernel 0: bake Hermitianized fp16 filter (UNSCALED) + twiddle table.
// ---------------------------------------------------------------------------
__global__ void k_bake_filter(const float* __restrict__ Hr, const float* __restrict__ Hi){
    int pw = blockIdx.x;          // 0..256
    int ph = threadIdx.x;         // 0..511
    if (pw == 0 && ph < 64){
        float s, c;
        sincosf(-6.283185307179586f * (float)ph / 512.0f, &s, &c);
        g_tws[ph] = make_float2(c, s);
    }
    int kh = kmap9(ph), kw = kmap9(pw);
    int nh = (512 - kh) & 511, nw = (512 - kw) & 511;
    int s0 = kh * 512 + kw;
    int s1 = nh * 512 + nw;
    float re = 0.25f * (Hr[s0] + Hr[s1]);
    float im = 0.25f * (Hi[s0] - Hi[s1]);
    g_filter_h[pw * 512 + ph] = pack_h2(re, im);   // NO INV_SCALE here (fp16 range!)
}

// ---------------------------------------------------------------------------
// Kernel 1: paired forward FFT along W. 64 threads = one FFT pair per block.
// ---------------------------------------------------------------------------
__global__ void __launch_bounds__(64) k_fft_rows(const float* __restrict__ x){
    __shared__ __half2 sP[HPL];
    __shared__ float2 tws[64];
    int t = threadIdx.x;
    tws[t] = g_tws[t];
    int pair = blockIdx.x;               // 0..32767
    int img  = pair >> 8;
    int h0   = (pair & 255) * 2;
    const float* x0 = x + (size_t)pair * 1024;
    const float* x1 = x0 + 512;

    u64c a[8];
    #pragma unroll
    for (int j = 0; j < 8; ++j) a[j] = pk2(x0[t + 64*j], x1[t + 64*j]);
    __syncthreads();   // tws ready

    fft512_fwd_h(a, sP, t, tws);

    __syncthreads();   // FFT's last plane reads done; plane reusable as staging
    #pragma unroll
    for (int q = 0; q < 8; ++q){ float2 f = up2(a[q]); sP[t + 64*q] = pack_h2(f.x, f.y); }
    __syncthreads();

    __half2* ib = g_scratch + (size_t)img * IMGS;
    int rr = t >> 3, tp = t & 7;
    #pragma unroll
    for (int q = 0; q < 4; ++q){
        int p = t + 64*q;
        int pm = p ? kmap9(512 - kmap9(p)) : 0;
        float2 A = unpack_h2(sP[p]);
        float2 B = unpack_h2(sP[pm]);
        unsigned off = (unsigned)(8*q + rr) * GRP + tp;
        ib[off + h0*8]       = pack_h2(A.x + B.x, A.y - B.y);
        ib[off + (h0+1)*8]   = pack_h2(A.y + B.y, B.x - A.x);
    }
    if (t == 0){   // p = 256, self-mirror: group 32, wi 0
        float2 A = unpack_h2(sP[256]);
        unsigned off = 32u * GRP;
        ib[off + h0*8]     = pack_h2(2.0f * A.x, 0.0f);
        ib[off + (h0+1)*8] = pack_h2(2.0f * A.y, 0.0f);
    }
}

// ---------------------------------------------------------------------------
// Kernel 2: per image, one group of 8 spectrum columns per block (256 thr).
// fp16 filter (unscaled) + separate packed INV_SCALE multiply.
// ---------------------------------------------------------------------------
#define SHP 513   // uint pitch per column in staging buffer (conflict-free)
__global__ void __launch_bounds__(256) k_cols(void){
    __shared__ __half2 sP[4][HPL];
    __shared__ unsigned sH[8 * SHP];
    __shared__ float2 tws[64];
    int tid = threadIdx.x;
    if (tid < 64) tws[tid] = g_tws[tid];

    int img = blockIdx.x / NGRP;
    int g   = blockIdx.x % NGRP;
    uint4* gbase = (uint4*)(g_scratch + (size_t)img * IMGS + (size_t)g * GRP);

    // stage-in: 1024 uint4 = 4096 half2 (full group), perfectly coalesced
    #pragma unroll
    for (int it = 0; it < 4; ++it){
        int idx = it * 256 + tid;        // 0..1023
        uint4 v = gbase[idx];
        int h  = idx >> 1;
        int wb = (idx & 1) * 4;
        sH[(wb+0)*SHP + h] = v.x;
        sH[(wb+1)*SHP + h] = v.y;
        sH[(wb+2)*SHP + h] = v.z;
        sH[(wb+3)*SHP + h] = v.w;
    }
    __syncthreads();

    int line = tid >> 6, t = tid & 63;
    const u64c invs = pk2(INV_SCALE, INV_SCALE);
    #pragma unroll
    for (int half = 0; half < 2; ++half){
        int wi = line + half * 4;
        u64c a[8];
        #pragma unroll
        for (int j = 0; j < 8; ++j){
            float2 f = unpack_u(sH[wi*SHP + t + 64*j]);
            a[j] = pk2(f.x, f.y);
        }

        fft512_fwd_h(a, sP[line], t, tws);   // first plane write safe: prior
                                             // sync (stage-in / end of half 0)

        int pw = g * 8 + wi; if (pw > 256) pw = 256;
        const __half2* frow = g_filter_h + (size_t)pw * 512 + t;
        #pragma unroll
        for (int q = 0; q < 8; ++q){
            a[q] = cmul_ps(a[q], unpack_h2(frow[64*q]));
            a[q] = mulp(a[q], invs);           // apply 1/512^2 in fp32 (fp16-safe)
        }

        __syncthreads();   // fwd's last plane reads done before inv writes

        fft512_inv_h(a, sP[line], t, tws);

        __syncthreads();   // inv's last plane reads done before next fwd / exit
        #pragma unroll
        for (int j = 0; j < 8; ++j){
            float2 f = up2(a[j]);
            sH[wi*SHP + t + 64*j] = pack_u(f.x, f.y);
        }
    }
    __syncthreads();

    // stage-out
    #pragma unroll
    for (int it = 0; it < 4; ++it){
        int idx = it * 256 + tid;
        int h  = idx >> 1;
        int wb = (idx & 1) * 4;
        uint4 v;
        v.x = sH[(wb+0)*SHP + h];
        v.y = sH[(wb+1)*SHP + h];
        v.z = sH[(wb+2)*SHP + h];
        v.w = sH[(wb+3)*SHP + h];
        gbase[idx] = v;
    }
}

// ---------------------------------------------------------------------------
// Kernel 3: paired inverse FFT along W (C2R x2). 64 threads = one pair per block.
// a[0..3] built straight from own global loads (no shared read-back).
// ---------------------------------------------------------------------------
__global__ void __launch_bounds__(64) k_ifft_rows(float* __restrict__ out){
    __shared__ __half2 sP[HPL];
    __shared__ float2 tws[64];
    int t = threadIdx.x;
    tws[t] = g_tws[t];
    int pair = blockIdx.x;
    int img  = pair >> 8;
    int h0   = (pair & 255) * 2;
    const __half2* ib = g_scratch + (size_t)img * IMGS;
    int rr = t >> 3, tp = t & 7;

    // load own 4 positions of each half-spectrum; also stage for mirror gathers
    __half2 v0[4], v1[4];
    #pragma unroll
    for (int j = 0; j < 4; ++j){
        int p = t + 64*j;
        unsigned off = (unsigned)(8*j + rr) * GRP + tp;
        v0[j] = ib[off + h0*8];
        v1[j] = ib[off + (h0+1)*8];
        sP[p]       = v0[j];
        sP[288 + p] = v1[j];
    }
    if (t == 0){
        unsigned off = 32u * GRP;
        sP[256]       = ib[off + h0*8];
        sP[288 + 256] = ib[off + (h0+1)*8];
    }
    __syncthreads();

    // build permuted Z:
    // p<=256: Z = S0[p] + i*S1[p];  p>256: Z = conj(S0[ps]) + i*conj(S1[ps])
    u64c a[8];
    #pragma unroll
    for (int q = 0; q < 4; ++q){           // own values, straight from registers
        float2 A = unpack_h2(v0[q]);
        float2 B = unpack_h2(v1[q]);
        a[q] = pk2(A.x - B.y, A.y + B.x);
    }
    #pragma unroll
    for (int q = 4; q < 8; ++q){
        int p = t + 64*q;
        if (p <= 256){                     // only t==0, q==4
            float2 A = unpack_h2(sP[p]);
            float2 B = unpack_h2(sP[288 + p]);
            a[q] = pk2(A.x - B.y, A.y + B.x);
        } else {
            int ps = kmap9(512 - kmap9(p));   // in [1,255]
            float2 A = unpack_h2(sP[ps]);
            float2 B = unpack_h2(sP[288 + ps]);
            a[q] = pk2(A.x + B.y, B.x - A.y);
        }
    }
    __syncthreads();   // staging reads done before inv FFT reuses plane

    fft512_inv_h(a, sP, t, tws);

    float* o0 = out + (size_t)pair * 1024;
    float* o1 = o0 + 512;
    #pragma unroll
    for (int j = 0; j < 8; ++j){
        float2 f = up2(a[j]);
        o0[t + 64*j] = f.x;
        o1[t + 64*j] = f.y;
    }
}

// ---------------------------------------------------------------------------
extern "C" void kernel_launch(void* const* d_in, const int* in_sizes, int n_in,
                              void* d_out, int out_size){
    const float* x  = (const float*)d_in[0];
    const float* Hr = (const float*)d_in[1];
    const float* Hi = (const float*)d_in[2];
    float* out = (float*)d_out;

    k_bake_filter<<<257, 512>>>(Hr, Hi);
    k_fft_rows<<<NROWS / 2, 64>>>(x);
    k_cols<<<NIMG * NGRP, 256>>>();
    k_ifft_rows<<<NROWS / 2, 64>>>(out);
}

// round 17
// speedup vs baseline: 1.0989x; 1.0226x over previous
#include <cuda_runtime.h>
#include <cuda_fp16.h>

#define DIM_H 512
#define NIMG  128
#define NROWS (NIMG * DIM_H)           // 65536 row-lines
#define INV_SCALE (1.0f / (512.0f * 512.0f))
#define HPL 584                         // half2 plane pitch (all kernels)
#define NGRP 33                         // column groups of 8 (257 cols padded to 264)
#define GRP  4096                       // half2 per group = 512*8
#define IMGS (NGRP * GRP)               // half2 per image = 135168

// Scratch: [img][group][h][wi] in fp16 complex, 69 MB. Group = 8 adjacent spectrum cols.
__device__ __half2 g_scratch[(size_t)NIMG * IMGS];
// Baked Hermitianized filter (fp32): [pw 0..256][ph 0..511], scale+untangle folded.
__device__ float2 g_filter[(size_t)257 * 512];
// Baked twiddles: g_tws[k] = exp(-2*pi*i*k/512), k in [0,64)
__device__ float2 g_tws[64];

// ---------------- packed f32x2 complex primitives ----------------
typedef unsigned long long u64c;   // one complex: lo = re, hi = im

__device__ __forceinline__ u64c pk2(float x, float y){
    u64c r; asm("mov.b64 %0, {%1, %2};" : "=l"(r) : "f"(x), "f"(y)); return r;
}
__device__ __forceinline__ float2 up2(u64c v){
    float2 r; asm("mov.b64 {%0, %1}, %2;" : "=f"(r.x), "=f"(r.y) : "l"(v)); return r;
}
__device__ __forceinline__ u64c addp(u64c a, u64c b){
    u64c r; asm("add.rn.f32x2 %0, %1, %2;" : "=l"(r) : "l"(a), "l"(b)); return r;
}
__device__ __forceinline__ u64c mulp(u64c a, u64c b){
    u64c r; asm("mul.rn.f32x2 %0, %1, %2;" : "=l"(r) : "l"(a), "l"(b)); return r;
}
__device__ __forceinline__ u64c fmap(u64c a, u64c b, u64c c){
    u64c r; asm("fma.rn.f32x2 %0, %1, %2, %3;" : "=l"(r) : "l"(a), "l"(b), "l"(c)); return r;
}
// a - b, exact (mul by -1 is exact, then .rn add)
__device__ __forceinline__ u64c subp(u64c a, u64c b){
    return fmap(b, pk2(-1.0f, -1.0f), a);
}
// rot<S>(v) = i*S*v
template<int S>
__device__ __forceinline__ u64c rotp(u64c v){
    float2 f = up2(v);
    return (S > 0) ? pk2(-f.y, f.x) : pk2(f.y, -f.x);
}

__device__ __forceinline__ float2 cmul(float2 a, float2 b){
    return make_float2(a.x*b.x - a.y*b.y, a.x*b.y + a.y*b.x);
}
__device__ __forceinline__ float2 cconj(float2 a){ return make_float2(a.x, -a.y); }
// packed * scalar-complex (twiddle/filter application)
__device__ __forceinline__ u64c cmul_ps(u64c a, float2 b){
    float2 f = up2(a);
    return pk2(f.x*b.x - f.y*b.y, f.x*b.y + f.y*b.x);
}

__device__ __forceinline__ __half2 pack_h2(float re, float im){ return __floats2half2_rn(re, im); }
__device__ __forceinline__ float2 unpack_h2(__half2 v){ return __half22float2(v); }
__device__ __forceinline__ float2 unpack_u(unsigned u){
    __half2 h = *reinterpret_cast<__half2*>(&u);
    return __half22float2(h);
}
__device__ __forceinline__ unsigned pack_u(float x, float y){
    __half2 h = __floats2half2_rn(x, y);
    return *reinterpret_cast<unsigned*>(&h);
}

// storage-position <-> frequency permutation: swap low two octal digits (involution, keeps bit 8)
__device__ __forceinline__ int kmap9(int p){
    return (p & 448) | ((p & 7) << 3) | ((p >> 3) & 7);
}

// 8-point DFT, packed, natural in/out: out[r] = sum_j in[j] * exp(S*2*pi*i*j*r/8)
template<int S>
__device__ __forceinline__ void dft8p(u64c* a){
    u64c t0=addp(a[0],a[4]), t1=subp(a[0],a[4]);
    u64c t2=addp(a[2],a[6]), t3=subp(a[2],a[6]);
    u64c t3r=rotp<S>(t3);
    u64c E0=addp(t0,t2), E2=subp(t0,t2), E1=addp(t1,t3r), E3=subp(t1,t3r);
    u64c u0=addp(a[1],a[5]), u1=subp(a[1],a[5]);
    u64c u2=addp(a[3],a[7]), u3=subp(a[3],a[7]);
    u64c u3r=rotp<S>(u3);
    u64c O0=addp(u0,u2), O2=subp(u0,u2), O1=addp(u1,u3r), O3=subp(u1,u3r);
    const float c = 0.70710678118654752f;
    u64c cc = pk2(c, c);
    O1 = mulp(cc, addp(O1, rotp<S>(O1)));          // *(c + i*S*c)
    u64c O2r = rotp<S>(O2);                         // *(i*S)
    O3 = mulp(cc, subp(rotp<S>(O3), O3));           // *(-c + i*S*c)
    a[0]=addp(E0,O0); a[4]=subp(E0,O0);
    a[1]=addp(E1,O1); a[5]=subp(E1,O1);
    a[2]=addp(E2,O2r); a[6]=subp(E2,O2r);
    a[3]=addp(E3,O3); a[7]=subp(E3,O3);
}

// Apply w^r to a[r], r=1..7. Powers scalar (dep depth 3), application packed-scalar.
__device__ __forceinline__ void apply7p(u64c* a, float2 w1){
    float2 w2 = cmul(w1, w1);
    float2 w3 = cmul(w2, w1);
    float2 w4 = cmul(w2, w2);
    float2 w5 = cmul(w3, w2);
    float2 w6 = cmul(w3, w3);
    float2 w7 = cmul(w4, w3);
    a[1]=cmul_ps(a[1],w1); a[2]=cmul_ps(a[2],w2); a[3]=cmul_ps(a[3],w3);
    a[4]=cmul_ps(a[4],w4); a[5]=cmul_ps(a[5],w5); a[6]=cmul_ps(a[6],w6);
    a[7]=cmul_ps(a[7],w7);
}

// Dual-state twiddle apply: powers computed ONCE for both register sets.
__device__ __forceinline__ void apply7p2(u64c* a, u64c* b, float2 w1){
    float2 w2 = cmul(w1, w1);
    float2 w3 = cmul(w2, w1);
    float2 w4 = cmul(w2, w2);
    float2 w5 = cmul(w3, w2);
    float2 w6 = cmul(w3, w3);
    float2 w7 = cmul(w4, w3);
    a[1]=cmul_ps(a[1],w1); b[1]=cmul_ps(b[1],w1);
    a[2]=cmul_ps(a[2],w2); b[2]=cmul_ps(b[2],w2);
    a[3]=cmul_ps(a[3],w3); b[3]=cmul_ps(b[3],w3);
    a[4]=cmul_ps(a[4],w4); b[4]=cmul_ps(b[4],w4);
    a[5]=cmul_ps(a[5],w5); b[5]=cmul_ps(b[5],w5);
    a[6]=cmul_ps(a[6],w6); b[6]=cmul_ps(b[6],w6);
    a[7]=cmul_ps(a[7],w7); b[7]=cmul_ps(b[7],w7);
}

// ---------- single-state fp16-plane FFTs (row kernels, as R13) ----------
__device__ __forceinline__ void fft512_fwd_h(u64c* a, __half2* pl, int t,
                                             const float2* tws){
    dft8p<-1>(a);
    apply7p(a, tws[t]);
    #pragma unroll
    for (int r = 0; r < 8; ++r){ float2 f = up2(a[r]); pl[r*72 + t] = pack_h2(f.x, f.y); }
    __syncthreads();
    int tp = t & 7, rr = t >> 3;
    #pragma unroll
    for (int j = 0; j < 8; ++j){ float2 f = unpack_h2(pl[rr*72 + tp + 8*j]); a[j] = pk2(f.x, f.y); }
    dft8p<-1>(a);
    apply7p(a, tws[tp*8]);
    __syncthreads();
    #pragma unroll
    for (int r1 = 0; r1 < 8; ++r1){ float2 f = up2(a[r1]); pl[rr*72 + r1*9 + tp] = pack_h2(f.x, f.y); }
    __syncthreads();
    #pragma unroll
    for (int k = 0; k < 8; ++k){ float2 f = unpack_h2(pl[t*9 + k]); a[k] = pk2(f.x, f.y); }
    dft8p<-1>(a);
}

__device__ __forceinline__ void fft512_inv_h(u64c* a, __half2* pl, int t,
                                             const float2* tws){
    dft8p<1>(a);
    int tp = t & 7, rr = t >> 3;
    #pragma unroll
    for (int k = 0; k < 8; ++k){ float2 f = up2(a[k]); pl[t*9 + k] = pack_h2(f.x, f.y); }
    __syncthreads();
    #pragma unroll
    for (int r1 = 0; r1 < 8; ++r1){ float2 f = unpack_h2(pl[rr*72 + r1*9 + tp]); a[r1] = pk2(f.x, f.y); }
    apply7p(a, cconj(tws[tp*8]));
    dft8p<1>(a);
    __syncthreads();
    #pragma unroll
    for (int j = 0; j < 8; ++j){ float2 f = up2(a[j]); pl[rr*72 + tp + 8*j] = pack_h2(f.x, f.y); }
    __syncthreads();
    #pragma unroll
    for (int r = 0; r < 8; ++r){ float2 f = unpack_h2(pl[r*72 + t]); a[r] = pk2(f.x, f.y); }
    apply7p(a, cconj(tws[t]));
    dft8p<1>(a);
}

// ---------- dual-state fp16-plane FFTs (cols kernel) ----------
__device__ __forceinline__ void fft512_fwd_h2(u64c* a, u64c* b,
                                              __half2* pa, __half2* pb, int t,
                                              const float2* tws){
    dft8p<-1>(a); dft8p<-1>(b);
    apply7p2(a, b, tws[t]);
    #pragma unroll
    for (int r = 0; r < 8; ++r){
        float2 f = up2(a[r]); pa[r*72 + t] = pack_h2(f.x, f.y);
        float2 g = up2(b[r]); pb[r*72 + t] = pack_h2(g.x, g.y);
    }
    __syncthreads();
    int tp = t & 7, rr = t >> 3;
    #pragma unroll
    for (int j = 0; j < 8; ++j){
        float2 f = unpack_h2(pa[rr*72 + tp + 8*j]); a[j] = pk2(f.x, f.y);
        float2 g = unpack_h2(pb[rr*72 + tp + 8*j]); b[j] = pk2(g.x, g.y);
    }
    dft8p<-1>(a); dft8p<-1>(b);
    apply7p2(a, b, tws[tp*8]);
    __syncthreads();
    #pragma unroll
    for (int r1 = 0; r1 < 8; ++r1){
        float2 f = up2(a[r1]); pa[rr*72 + r1*9 + tp] = pack_h2(f.x, f.y);
        float2 g = up2(b[r1]); pb[rr*72 + r1*9 + tp] = pack_h2(g.x, g.y);
    }
    __syncthreads();
    #pragma unroll
    for (int k = 0; k < 8; ++k){
        float2 f = unpack_h2(pa[t*9 + k]); a[k] = pk2(f.x, f.y);
        float2 g = unpack_h2(pb[t*9 + k]); b[k] = pk2(g.x, g.y);
    }
    dft8p<-1>(a); dft8p<-1>(b);
}

__device__ __forceinline__ void fft512_inv_h2(u64c* a, u64c* b,
                                              __half2* pa, __half2* pb, int t,
                                              const float2* tws){
    dft8p<1>(a); dft8p<1>(b);
    int tp = t & 7, rr = t >> 3;
    #pragma unroll
    for (int k = 0; k < 8; ++k){
        float2 f = up2(a[k]); pa[t*9 + k] = pack_h2(f.x, f.y);
        float2 g = up2(b[k]); pb[t*9 + k] = pack_h2(g.x, g.y);
    }
    __syncthreads();
    #pragma unroll
    for (int r1 = 0; r1 < 8; ++r1){
        float2 f = unpack_h2(pa[rr*72 + r1*9 + tp]); a[r1] = pk2(f.x, f.y);
        float2 g = unpack_h2(pb[rr*72 + r1*9 + tp]); b[r1] = pk2(g.x, g.y);
    }
    apply7p2(a, b, cconj(tws[tp*8]));
    dft8p<1>(a); dft8p<1>(b);
    __syncthreads();
    #pragma unroll
    for (int j = 0; j < 8; ++j){
        float2 f = up2(a[j]); pa[rr*72 + tp + 8*j] = pack_h2(f.x, f.y);
        float2 g = up2(b[j]); pb[rr*72 + tp + 8*j] = pack_h2(g.x, g.y);
    }
    __syncthreads();
    #pragma unroll
    for (int r = 0; r < 8; ++r){
        float2 f = unpack_h2(pa[r*72 + t]); a[r] = pk2(f.x, f.y);
        float2 g = unpack_h2(pb[r*72 + t]); b[r] = pk2(g.x, g.y);
    }
    apply7p2(a, b, cconj(tws[t]));
    dft8p<1>(a); dft8p<1>(b);
}

// ---------------------------------------------------------------------------
// Kernel 0: bake Hermitianized fp32 filter (scale folded) + twiddle table.
// ---------------------------------------------------------------------------
__global__ void k_bake_filter(const float* __restrict__ Hr, const float* __restrict__ Hi){
    int pw = blockIdx.x;          // 0..256
    int ph = threadIdx.x;         // 0..511
    if (pw == 0 && ph < 64){
        float s, c;
        sincosf(-6.283185307179586f * (float)ph / 512.0f, &s, &c);
        g_tws[ph] = make_float2(c, s);
    }
    int kh = kmap9(ph), kw = kmap9(pw);
    int nh = (512 - kh) & 511, nw = (512 - kw) & 511;
    int s0 = kh * 512 + kw;
    int s1 = nh * 512 + nw;
    float re = 0.25f * (Hr[s0] + Hr[s1]);
    float im = 0.25f * (Hi[s0] - Hi[s1]);
    g_filter[pw * 512 + ph] = make_float2(re * INV_SCALE, im * INV_SCALE);
}

// ---------------------------------------------------------------------------
// Kernel 1: paired forward FFT along W. 64 threads = one FFT pair per block.
// ---------------------------------------------------------------------------
__global__ void __launch_bounds__(64) k_fft_rows(const float* __restrict__ x){
    __shared__ __half2 sP[HPL];
    __shared__ float2 tws[64];
    int t = threadIdx.x;
    tws[t] = g_tws[t];
    int pair = blockIdx.x;               // 0..32767
    int img  = pair >> 8;
    int h0   = (pair & 255) * 2;
    const float* x0 = x + (size_t)pair * 1024;
    const float* x1 = x0 + 512;

    u64c a[8];
    #pragma unroll
    for (int j = 0; j < 8; ++j) a[j] = pk2(x0[t + 64*j], x1[t + 64*j]);
    __syncthreads();   // tws ready

    fft512_fwd_h(a, sP, t, tws);

    __syncthreads();   // FFT's last plane reads done; plane reusable as staging
    #pragma unroll
    for (int q = 0; q < 8; ++q){ float2 f = up2(a[q]); sP[t + 64*q] = pack_h2(f.x, f.y); }
    __syncthreads();

    __half2* ib = g_scratch + (size_t)img * IMGS;
    int rr = t >> 3, tp = t & 7;
    #pragma unroll
    for (int q = 0; q < 4; ++q){
        int p = t + 64*q;
        int pm = p ? kmap9(512 - kmap9(p)) : 0;
        float2 A = unpack_h2(sP[p]);
        float2 B = unpack_h2(sP[pm]);
        unsigned off = (unsigned)(8*q + rr) * GRP + tp;
        ib[off + h0*8]       = pack_h2(A.x + B.x, A.y - B.y);
        ib[off + (h0+1)*8]   = pack_h2(A.y + B.y, B.x - A.x);
    }
    if (t == 0){   // p = 256, self-mirror: group 32, wi 0
        float2 A = unpack_h2(sP[256]);
        unsigned off = 32u * GRP;
        ib[off + h0*8]     = pack_h2(2.0f * A.x, 0.0f);
        ib[off + (h0+1)*8] = pack_h2(2.0f * A.y, 0.0f);
    }
}

// ---------------------------------------------------------------------------
// Kernel 2: per image, one group of 8 spectrum columns per block (256 thr).
// Each 64-thread line processes its TWO columns (wi, wi+4) INTERLEAVED:
// shared barriers, shared twiddle powers, doubled ILP.
// ---------------------------------------------------------------------------
#define SHP 513   // uint pitch per column in staging buffer (conflict-free)
__global__ void __launch_bounds__(256) k_cols(void){
    __shared__ __half2 sP[8][HPL];
    __shared__ unsigned sH[8 * SHP];
    __shared__ float2 tws[64];
    int tid = threadIdx.x;
    if (tid < 64) tws[tid] = g_tws[tid];

    int img = blockIdx.x / NGRP;
    int g   = blockIdx.x % NGRP;
    uint4* gbase = (uint4*)(g_scratch + (size_t)img * IMGS + (size_t)g * GRP);

    // stage-in: 1024 uint4 = 4096 half2 (full group), perfectly coalesced
    #pragma unroll
    for (int it = 0; it < 4; ++it){
        int idx = it * 256 + tid;        // 0..1023
        uint4 v = gbase[idx];
        int h  = idx >> 1;
        int wb = (idx & 1) * 4;
        sH[(wb+0)*SHP + h] = v.x;
        sH[(wb+1)*SHP + h] = v.y;
        sH[(wb+2)*SHP + h] = v.z;
        sH[(wb+3)*SHP + h] = v.w;
    }
    __syncthreads();

    int line = tid >> 6, t = tid & 63;
    int wa = line, wb2 = line + 4;
    u64c a[8], b[8];
    #pragma unroll
    for (int j = 0; j < 8; ++j){
        float2 f = unpack_u(sH[wa*SHP + t + 64*j]);  a[j] = pk2(f.x, f.y);
        float2 g2 = unpack_u(sH[wb2*SHP + t + 64*j]); b[j] = pk2(g2.x, g2.y);
    }

    fft512_fwd_h2(a, b, sP[line], sP[line+4], t, tws);  // first write safe: stage-in sync

    int pwa = g * 8 + wa;  if (pwa > 256) pwa = 256;
    int pwb = g * 8 + wb2; if (pwb > 256) pwb = 256;
    const float2* fra = g_filter + (size_t)pwa * 512 + t;
    const float2* frb = g_filter + (size_t)pwb * 512 + t;
    #pragma unroll
    for (int q = 0; q < 8; ++q){
        a[q] = cmul_ps(a[q], fra[64*q]);
        b[q] = cmul_ps(b[q], frb[64*q]);
    }

    __syncthreads();   // fwd's last plane reads done before inv writes

    fft512_inv_h2(a, b, sP[line], sP[line+4], t, tws);

    __syncthreads();   // inv's last plane reads done before staging writes
    #pragma unroll
    for (int j = 0; j < 8; ++j){
        float2 f = up2(a[j]);  sH[wa*SHP + t + 64*j]  = pack_u(f.x, f.y);
        float2 g2 = up2(b[j]); sH[wb2*SHP + t + 64*j] = pack_u(g2.x, g2.y);
    }
    __syncthreads();

    // stage-out
    #pragma unroll
    for (int it = 0; it < 4; ++it){
        int idx = it * 256 + tid;
        int h  = idx >> 1;
        int wb = (idx & 1) * 4;
        uint4 v;
        v.x = sH[(wb+0)*SHP + h];
        v.y = sH[(wb+1)*SHP + h];
        v.z = sH[(wb+2)*SHP + h];
        v.w = sH[(wb+3)*SHP + h];
        gbase[idx] = v;
    }
}

// ---------------------------------------------------------------------------
// Kernel 3: paired inverse FFT along W (C2R x2). 64 threads = one pair per block.
// a[0..3] built straight from own global loads (no shared read-back).
// ---------------------------------------------------------------------------
__global__ void __launch_bounds__(64) k_ifft_rows(float* __restrict__ out){
    __shared__ __half2 sP[HPL];
    __shared__ float2 tws[64];
    int t = threadIdx.x;
    tws[t] = g_tws[t];
    int pair = blockIdx.x;
    int img  = pair >> 8;
    int h0   = (pair & 255) * 2;
    const __half2* ib = g_scratch + (size_t)img * IMGS;
    int rr = t >> 3, tp = t & 7;

    // load own 4 positions of each half-spectrum; also stage for mirror gathers
    __half2 v0[4], v1[4];
    #pragma unroll
    for (int j = 0; j < 4; ++j){
        int p = t + 64*j;
        unsigned off = (unsigned)(8*j + rr) * GRP + tp;
        v0[j] = ib[off + h0*8];
        v1[j] = ib[off + (h0+1)*8];
        sP[p]       = v0[j];
        sP[288 + p] = v1[j];
    }
    if (t == 0){
        unsigned off = 32u * GRP;
        sP[256]       = ib[off + h0*8];
        sP[288 + 256] = ib[off + (h0+1)*8];
    }
    __syncthreads();

    // build permuted Z:
    // p<=256: Z = S0[p] + i*S1[p];  p>256: Z = conj(S0[ps]) + i*conj(S1[ps])
    u64c a[8];
    #pragma unroll
    for (int q = 0; q < 4; ++q){           // own values, straight from registers
        float2 A = unpack_h2(v0[q]);
        float2 B = unpack_h2(v1[q]);
        a[q] = pk2(A.x - B.y, A.y + B.x);
    }
    #pragma unroll
    for (int q = 4; q < 8; ++q){
        int p = t + 64*q;
        if (p <= 256){                     // only t==0, q==4
            float2 A = unpack_h2(sP[p]);
            float2 B = unpack_h2(sP[288 + p]);
            a[q] = pk2(A.x - B.y, A.y + B.x);
        } else {
            int ps = kmap9(512 - kmap9(p));   // in [1,255]
            float2 A = unpack_h2(sP[ps]);
            float2 B = unpack_h2(sP[288 + ps]);
            a[q] = pk2(A.x + B.y, B.x - A.y);
        }
    }
    __syncthreads();   // staging reads done before inv FFT reuses plane

    fft512_inv_h(a, sP, t, tws);

    float* o0 = out + (size_t)pair * 1024;
    float* o1 = o0 + 512;
    #pragma unroll
    for (int j = 0; j < 8; ++j){
        float2 f = up2(a[j]);
        o0[t + 64*j] = f.x;
        o1[t + 64*j] = f.y;
    }
}

// ---------------------------------------------------------------------------
extern "C" void kernel_launch(void* const* d_in, const int* in_sizes, int n_in,
                              void* d_out, int out_size){
    const float* x  = (const float*)d_in[0];
    const float* Hr = (const float*)d_in[1];
    const float* Hi = (const float*)d_in[2];
    float* out = (float*)d_out;

    k_bake_filter<<<257, 512>>>(Hr, Hi);
    k_fft_rows<<<NROWS / 2, 64>>>(x);
    k_cols<<<NIMG * NGRP, 256>>>();
    k_ifft_rows<<<NROWS / 2, 64>>>(out);
}